// round 1
// baseline (speedup 1.0000x reference)
#include <cuda_runtime.h>
#include <cuda_bf16.h>
#include <math.h>

// Problem constants
#define BB 2
#define TT 2048
#define DD 2048
#define HH 16
#define DKq 64
#define DVv 128
#define RR 16
#define CC 64
#define NCC 32
#define MM (BB*TT)          // 4096
#define NQK (HH*DKq)        // 1024
#define NV  (HH*DVv)        // 2048
#define GLN_INV (1.0f/16.0f)
#define EPSL 1e-5f

// ---------------- scratch (device globals, no allocs allowed) ----------------
__device__ float g_q [MM*NQK];
__device__ float g_k [MM*NQK];
__device__ float g_v [MM*NV];
__device__ float g_gk[MM*NQK];
__device__ float g_r1[MM*RR];
__device__ float g_r2[MM*RR];
__device__ float g_g [MM*NV];
__device__ float g_o [MM*NV];

// ---------------- SGEMM: C = act(A[M,K] @ W[K,N]) ----------------
// BM=BN=128, BK=16, 256 threads, 8x8 per thread.
template<bool SILU>
__global__ __launch_bounds__(256) void sgemm_kernel(
    const float* __restrict__ A, const float* __restrict__ W,
    float* __restrict__ C, int M, int N, int K)
{
    __shared__ float As[16][132];   // transposed A tile, padded
    __shared__ float Bs[16][128];

    const int tid = threadIdx.x;
    const int bm = blockIdx.y * 128;
    const int bn = blockIdx.x * 128;
    const int ty = tid >> 4;       // 0..15
    const int tx = tid & 15;       // 0..15

    float acc[8][8];
#pragma unroll
    for (int i = 0; i < 8; i++)
#pragma unroll
        for (int j = 0; j < 8; j++) acc[i][j] = 0.f;

    const float* Ap = A + (long)bm * K;
    const float* Wp = W + bn;

    for (int k0 = 0; k0 < K; k0 += 16) {
#pragma unroll
        for (int i = 0; i < 2; i++) {
            int f = i * 256 + tid;              // 0..511
            int row = f >> 2;                   // 0..127
            int kq  = (f & 3) << 2;             // 0,4,8,12
            float4 a4 = *(const float4*)(Ap + (long)row * K + k0 + kq);
            As[kq + 0][row] = a4.x;
            As[kq + 1][row] = a4.y;
            As[kq + 2][row] = a4.z;
            As[kq + 3][row] = a4.w;
            int krow = f >> 5;                  // 0..15
            int nq   = (f & 31) << 2;           // 0..124
            float4 b4 = *(const float4*)(Wp + (long)(k0 + krow) * N + nq);
            *(float4*)&Bs[krow][nq] = b4;
        }
        __syncthreads();
#pragma unroll
        for (int kk = 0; kk < 16; kk++) {
            float a[8], b[8];
            *(float4*)(a)     = *(float4*)&As[kk][ty * 8];
            *(float4*)(a + 4) = *(float4*)&As[kk][ty * 8 + 4];
            *(float4*)(b)     = *(float4*)&Bs[kk][tx * 8];
            *(float4*)(b + 4) = *(float4*)&Bs[kk][tx * 8 + 4];
#pragma unroll
            for (int i = 0; i < 8; i++)
#pragma unroll
                for (int j = 0; j < 8; j++) acc[i][j] += a[i] * b[j];
        }
        __syncthreads();
    }

#pragma unroll
    for (int i = 0; i < 8; i++) {
        float out[8];
#pragma unroll
        for (int j = 0; j < 8; j++) {
            float x = acc[i][j];
            if (SILU) x = x / (1.f + __expf(-x));
            out[j] = x;
        }
        float* cp = C + (long)(bm + ty * 8 + i) * N + bn + tx * 8;
        *(float4*)(cp)     = *(float4*)(out);
        *(float4*)(cp + 4) = *(float4*)(out + 4);
    }
}

// ---------------- low-rank stage 1: R[M,16] = A[M,K] @ W[K,16] ----------------
__global__ __launch_bounds__(256) void lowrank1_kernel(
    const float* __restrict__ A, const float* __restrict__ W,
    float* __restrict__ Rt, int K)
{
    const int warp = threadIdx.x >> 5;
    const int lane = threadIdx.x & 31;
    const int m0 = blockIdx.x * 32 + warp * 4;

    float acc[4][16];
#pragma unroll
    for (int r = 0; r < 4; r++)
#pragma unroll
        for (int n = 0; n < 16; n++) acc[r][n] = 0.f;

    for (int k = lane; k < K; k += 32) {
        float a0 = A[(long)(m0 + 0) * K + k];
        float a1 = A[(long)(m0 + 1) * K + k];
        float a2 = A[(long)(m0 + 2) * K + k];
        float a3 = A[(long)(m0 + 3) * K + k];
        const float4* wr = (const float4*)(W + (long)k * 16);
        float4 w0 = wr[0], w1 = wr[1], w2 = wr[2], w3 = wr[3];
        float w[16] = {w0.x,w0.y,w0.z,w0.w, w1.x,w1.y,w1.z,w1.w,
                       w2.x,w2.y,w2.z,w2.w, w3.x,w3.y,w3.z,w3.w};
#pragma unroll
        for (int n = 0; n < 16; n++) {
            acc[0][n] += a0 * w[n];
            acc[1][n] += a1 * w[n];
            acc[2][n] += a2 * w[n];
            acc[3][n] += a3 * w[n];
        }
    }
#pragma unroll
    for (int r = 0; r < 4; r++)
#pragma unroll
        for (int n = 0; n < 16; n++) {
            float v = acc[r][n];
            v += __shfl_xor_sync(0xffffffffu, v, 16);
            v += __shfl_xor_sync(0xffffffffu, v, 8);
            v += __shfl_xor_sync(0xffffffffu, v, 4);
            v += __shfl_xor_sync(0xffffffffu, v, 2);
            v += __shfl_xor_sync(0xffffffffu, v, 1);
            if (lane == 0) Rt[(long)(m0 + r) * 16 + n] = v;
        }
}

// ---------------- low-rank stage 2: Out = act(R[M,16] @ W2[16,N] + b) ----------------
// mode 0: raw; mode 1: log_sigmoid(x)/GLN
__global__ __launch_bounds__(256) void lowrank2_kernel(
    const float* __restrict__ Rt, const float* __restrict__ W2,
    const float* __restrict__ bias, float* __restrict__ Out,
    int NOUT, int mode)
{
    int idx = blockIdx.x * 256 + threadIdx.x;
    int m = idx / NOUT;
    int n = idx - m * NOUT;
    const float* r = Rt + (long)m * 16;
    float acc = bias[n];
#pragma unroll
    for (int j = 0; j < 16; j++) acc += r[j] * W2[(long)j * NOUT + n];
    if (mode) {
        float x = acc;
        float ls = (x >= 0.f) ? -log1pf(__expf(-x)) : (x - log1pf(__expf(x)));
        acc = ls * GLN_INV;
    }
    Out[idx] = acc;
}

// ---------------- GLA chunked recurrence ----------------
// grid = B*H*NSPLIT blocks, 256 threads.  NSPLIT=4 -> DVs=32 per block.
// Shared layout (floats): sq[64][65], sk[64][65], sA[64][65] (also gk/G),
//                          sv[64][33], sS[64][33], sGl[64]
#define OFF_Q  0
#define OFF_K  4160
#define OFF_A  8320
#define OFF_V  12480
#define OFF_S  14592
#define OFF_GL 16704
#define SM_FLOATS 16768
#define SM_BYTES  (SM_FLOATS * 4)

__global__ __launch_bounds__(256) void gla_kernel(
    const float* __restrict__ Q, const float* __restrict__ Kx,
    const float* __restrict__ V, const float* __restrict__ GK,
    float* __restrict__ O)
{
    extern __shared__ float sm[];
    float* sq  = sm + OFF_Q;
    float* sk  = sm + OFF_K;
    float* sA  = sm + OFF_A;
    float* sv  = sm + OFF_V;
    float* sS  = sm + OFF_S;
    float* sGl = sm + OFF_GL;

    const int tid = threadIdx.x;
    const int s  = blockIdx.x & 3;
    const int bh = blockIdx.x >> 2;
    const int h  = bh & 15;
    const int b  = bh >> 4;
    const int e0 = s * 32;

    const int cb = tid & 63;    // c-row (or d-row) role
    const int eg = tid >> 6;    // 0..3, owns e = eg*8..eg*8+7

    // zero state
    for (int i = tid; i < 64 * 33; i += 256) sS[i] = 0.f;

    for (int ch = 0; ch < NCC; ch++) {
        __syncthreads();
        const long base = ((long)(b * TT + ch * 64) * HH + h);
        const float* qp  = Q  + base * DKq;   // row stride H*DK = 1024
        const float* kp  = Kx + base * DKq;
        const float* gp  = GK + base * DKq;
        const float* vp  = V  + base * DVv + e0;  // row stride H*DV = 2048

        // load q,k,gk (64x64 each) and v (64x32)
#pragma unroll
        for (int w = 0; w < 4; w++) {
            int f = w * 256 + tid;
            int c = f >> 4;
            int dq = (f & 15) << 2;
            float4 a4 = *(const float4*)(qp + (long)c * 1024 + dq);
            sq[c*65+dq]=a4.x; sq[c*65+dq+1]=a4.y; sq[c*65+dq+2]=a4.z; sq[c*65+dq+3]=a4.w;
            float4 b4 = *(const float4*)(kp + (long)c * 1024 + dq);
            sk[c*65+dq]=b4.x; sk[c*65+dq+1]=b4.y; sk[c*65+dq+2]=b4.z; sk[c*65+dq+3]=b4.w;
            float4 g4 = *(const float4*)(gp + (long)c * 1024 + dq);
            sA[c*65+dq]=g4.x; sA[c*65+dq+1]=g4.y; sA[c*65+dq+2]=g4.z; sA[c*65+dq+3]=g4.w;
        }
#pragma unroll
        for (int w = 0; w < 2; w++) {
            int f = w * 256 + tid;
            int c = f >> 3;
            int eq = (f & 7) << 2;
            float4 v4 = *(const float4*)(vp + (long)c * 2048 + eq);
            sv[c*33+eq]=v4.x; sv[c*33+eq+1]=v4.y; sv[c*33+eq+2]=v4.z; sv[c*33+eq+3]=v4.w;
        }
        __syncthreads();

        // cumsum of gk along c (in place in sA); store raw last into sGl
        if (tid < 64) {
            int d = tid;
            float acc = 0.f;
            for (int c = 0; c < 64; c++) {
                acc += sA[c*65 + d];
                sA[c*65 + d] = acc;
            }
            sGl[d] = acc;
        }
        __syncthreads();

        // transform: qg = q*exp(G)*DK^-0.5 ; kg = k*exp(-G); sGl -> exp(Glast)
#pragma unroll
        for (int w = 0; w < 16; w++) {
            int f = w * 256 + tid;
            int c = f >> 6;
            int d = f & 63;
            float G = sA[c*65 + d];
            sq[c*65 + d] *= __expf(G) * 0.125f;
            sk[c*65 + d] *= __expf(-G);
        }
        if (tid < 64) sGl[tid] = __expf(sGl[tid]);
        __syncthreads();

        // o_inter = qg @ S  (reads previous S)
        float o_r[8];
#pragma unroll
        for (int j = 0; j < 8; j++) o_r[j] = 0.f;
        {
            const int c = cb;
#pragma unroll 4
            for (int d = 0; d < 64; d++) {
                float qv = sq[c*65 + d];
                const float* Srow = &sS[d*33 + eg*8];
#pragma unroll
                for (int j = 0; j < 8; j++) o_r[j] += qv * Srow[j];
            }
        }
        // A = qg @ kg^T (lower triangular incl diag); overwrites sA (G dead)
        {
            const int c = cb;
            const int jbase = eg * 16;
            float a[16];
#pragma unroll
            for (int jj = 0; jj < 16; jj++) a[jj] = 0.f;
#pragma unroll 2
            for (int d = 0; d < 64; d++) {
                float qv = sq[c*65 + d];
#pragma unroll
                for (int jj = 0; jj < 16; jj++)
                    a[jj] += qv * sk[(jbase + jj)*65 + d];
            }
#pragma unroll
            for (int jj = 0; jj < 16; jj++)
                sA[c*65 + jbase + jj] = (jbase + jj <= c) ? a[jj] : 0.f;
        }
        __syncthreads();

        // o_intra = A @ v ; write o chunk
        {
            const int c = cb;
            for (int j64 = 0; j64 <= c; j64++) {
                float a = sA[c*65 + j64];
                const float* vr = &sv[j64*33 + eg*8];
#pragma unroll
                for (int j = 0; j < 8; j++) o_r[j] += a * vr[j];
            }
            float* op = O + (base + (long)c * HH) * DVv + e0 + eg * 8;
            float4 w0 = make_float4(o_r[0], o_r[1], o_r[2], o_r[3]);
            float4 w1 = make_float4(o_r[4], o_r[5], o_r[6], o_r[7]);
            *(float4*)(op)     = w0;
            *(float4*)(op + 4) = w1;
        }
        // S update: S[d][e] = expGl[d] * (S[d][e] + sum_c kg[c][d]*v[c][e])
        {
            const int d = cb;
            float* Srow = &sS[d*33 + eg*8];
            float acc[8];
#pragma unroll
            for (int j = 0; j < 8; j++) acc[j] = Srow[j];
#pragma unroll 4
            for (int c64 = 0; c64 < 64; c64++) {
                float kv = sk[c64*65 + d];
                const float* vr = &sv[c64*33 + eg*8];
#pragma unroll
                for (int j = 0; j < 8; j++) acc[j] += kv * vr[j];
            }
            float eGl = sGl[d];
#pragma unroll
            for (int j = 0; j < 8; j++) Srow[j] = acc[j] * eGl;
        }
    }
}

// ---------------- RMS norm over DV + sigmoid gate (in place on O) ----------------
__global__ __launch_bounds__(256) void rmsgate_kernel(
    float* __restrict__ O, const float* __restrict__ G,
    const float* __restrict__ gw)
{
    int row = blockIdx.x * 8 + (threadIdx.x >> 5);
    int lane = threadIdx.x & 31;
    long basei = (long)row * 128 + lane * 4;
    float4 o4 = *(float4*)&O[basei];
    float ss = o4.x*o4.x + o4.y*o4.y + o4.z*o4.z + o4.w*o4.w;
    ss += __shfl_xor_sync(0xffffffffu, ss, 16);
    ss += __shfl_xor_sync(0xffffffffu, ss, 8);
    ss += __shfl_xor_sync(0xffffffffu, ss, 4);
    ss += __shfl_xor_sync(0xffffffffu, ss, 2);
    ss += __shfl_xor_sync(0xffffffffu, ss, 1);
    float rr = rsqrtf(ss * (1.f / 128.f) + EPSL);
    float4 g4 = *(const float4*)&G[basei];
    float4 w4 = *(const float4*)&gw[lane * 4];
    o4.x = o4.x * rr * w4.x / (1.f + __expf(-g4.x));
    o4.y = o4.y * rr * w4.y / (1.f + __expf(-g4.y));
    o4.z = o4.z * rr * w4.z / (1.f + __expf(-g4.z));
    o4.w = o4.w * rr * w4.w / (1.f + __expf(-g4.w));
    *(float4*)&O[basei] = o4;
}

// ---------------- launch ----------------
extern "C" void kernel_launch(void* const* d_in, const int* in_sizes, int n_in,
                              void* d_out, int out_size)
{
    const float* hs    = (const float*)d_in[0];
    const float* Wq    = (const float*)d_in[1];
    const float* Wk    = (const float*)d_in[2];
    const float* Wv    = (const float*)d_in[3];
    const float* Wgk1  = (const float*)d_in[4];
    const float* Wgk2  = (const float*)d_in[5];
    const float* bgk2  = (const float*)d_in[6];
    const float* Wg1   = (const float*)d_in[7];
    const float* Wg2   = (const float*)d_in[8];
    const float* bg2   = (const float*)d_in[9];
    const float* Wo    = (const float*)d_in[10];
    const float* gnw   = (const float*)d_in[11];
    float* out = (float*)d_out;

    float *pq, *pk, *pv, *pgk, *pr1, *pr2, *pg, *po;
    cudaGetSymbolAddress((void**)&pq,  g_q);
    cudaGetSymbolAddress((void**)&pk,  g_k);
    cudaGetSymbolAddress((void**)&pv,  g_v);
    cudaGetSymbolAddress((void**)&pgk, g_gk);
    cudaGetSymbolAddress((void**)&pr1, g_r1);
    cudaGetSymbolAddress((void**)&pr2, g_r2);
    cudaGetSymbolAddress((void**)&pg,  g_g);
    cudaGetSymbolAddress((void**)&po,  g_o);

    // projections with silu
    {
        dim3 grid(NQK / 128, MM / 128);
        sgemm_kernel<true><<<grid, 256>>>(hs, Wq, pq, MM, NQK, DD);
        sgemm_kernel<true><<<grid, 256>>>(hs, Wk, pk, MM, NQK, DD);
    }
    {
        dim3 grid(NV / 128, MM / 128);
        sgemm_kernel<true><<<grid, 256>>>(hs, Wv, pv, MM, NV, DD);
    }
    // low-rank gk gate
    lowrank1_kernel<<<MM / 32, 256>>>(hs, Wgk1, pr1, DD);
    lowrank2_kernel<<<(MM * NQK) / 256, 256>>>(pr1, Wgk2, bgk2, pgk, NQK, 1);
    // low-rank output gate (raw, sigmoid applied later)
    lowrank1_kernel<<<MM / 32, 256>>>(hs, Wg1, pr2, DD);
    lowrank2_kernel<<<(MM * NV) / 256, 256>>>(pr2, Wg2, bg2, pg, NV, 0);

    // chunked GLA
    cudaFuncSetAttribute(gla_kernel, cudaFuncAttributeMaxDynamicSharedMemorySize, SM_BYTES);
    gla_kernel<<<BB * HH * 4, 256, SM_BYTES>>>(pq, pk, pv, pgk, po);

    // rms norm + gate
    rmsgate_kernel<<<(MM * HH) / 8, 256>>>(po, pg, gnw);

    // output projection
    {
        dim3 grid(NV / 128, MM / 128);
        sgemm_kernel<false><<<grid, 256>>>(po, Wo, out, MM, DD, NV);
    }
    (void)in_sizes; (void)n_in; (void)out_size;
}

// round 3
// speedup vs baseline: 1.9989x; 1.9989x over previous
#include <cuda_runtime.h>
#include <cuda_bf16.h>
#include <math.h>
#include <stdint.h>

// Problem constants
#define BB 2
#define TT 2048
#define DD 2048
#define HH 16
#define DKq 64
#define DVv 128
#define RR 16
#define CC 64
#define NCC 32
#define MM (BB*TT)          // 4096
#define NQK (HH*DKq)        // 1024
#define NV  (HH*DVv)        // 2048
#define GLN_INV (1.0f/16.0f)
#define EPSL 1e-5f

// ---------------- scratch (device globals, no allocs allowed) ----------------
__device__ float g_q [MM*NQK];
__device__ float g_k [MM*NQK];
__device__ float g_v [MM*NV];
__device__ float g_gk[MM*NQK];
__device__ float g_r1[MM*RR];
__device__ float g_r2[MM*RR];
__device__ float g_g [MM*NV];
__device__ float g_o [MM*NV];
// tf32-rounded operand copies
__device__ float g_hsr[MM*DD];
__device__ float g_wqr[DD*NQK];
__device__ float g_wkr[DD*NQK];
__device__ float g_wvr[DD*NV];
__device__ float g_wor[NV*DD];

// ---------------- helpers ----------------
__device__ __forceinline__ float f2tf32(float x) {
    uint32_t r;
    asm("cvt.rna.tf32.f32 %0, %1;" : "=r"(r) : "f"(x));
    return __uint_as_float(r);
}

__device__ __forceinline__ void cp16(void* smem_dst, const void* gmem_src) {
    uint32_t s = (uint32_t)__cvta_generic_to_shared(smem_dst);
    asm volatile("cp.async.cg.shared.global [%0], [%1], 16;" :: "r"(s), "l"(gmem_src));
}

// elementwise rna-round to tf32 (copy)
__global__ __launch_bounds__(256) void round_tf32_kernel(
    const float* __restrict__ src, float* __restrict__ dst, int n4)
{
    int i = blockIdx.x * 256 + threadIdx.x;
    if (i < n4) {
        float4 v = ((const float4*)src)[i];
        v.x = f2tf32(v.x); v.y = f2tf32(v.y);
        v.z = f2tf32(v.z); v.w = f2tf32(v.w);
        ((float4*)dst)[i] = v;
    }
}

// ---------------- tf32 tensor-core GEMM: C = act(A[M,K] @ B[K,N]) -----------
// A, B must be pre-rounded to tf32. BM=128, BN=256, BK=32, 256 thr (8 warps),
// warp tile 64x64 (mma m16n8k8), cp.async double-buffered smem.
#define GA_STRIDE 36      // 32 + 4 pad (floats)
#define GB_STRIDE 264     // 256 + 8 pad (floats)
#define GSM_A (128*GA_STRIDE)
#define GSM_B (32*GB_STRIDE)
#define GSM_BYTES ((2*GSM_A + 2*GSM_B)*4)

template<bool SILU>
__global__ __launch_bounds__(256, 1) void tf32gemm_kernel(
    const float* __restrict__ A, const float* __restrict__ B,
    float* __restrict__ C, int M, int N, int K)
{
    extern __shared__ float sm[];
    float* As[2] = { sm, sm + GSM_A };
    float* Bs[2] = { sm + 2*GSM_A, sm + 2*GSM_A + GSM_B };

    const int tid  = threadIdx.x;
    const int warp = tid >> 5;
    const int lane = tid & 31;
    const int g    = lane >> 2;     // 0..7
    const int tig  = lane & 3;      // 0..3
    const int wm   = (warp >> 2) * 64;   // 0 or 64
    const int wn   = (warp & 3) * 64;    // 0,64,128,192
    const int bm   = blockIdx.y * 128;
    const int bn   = blockIdx.x * 256;

    float c[4][8][4];
#pragma unroll
    for (int mt = 0; mt < 4; mt++)
#pragma unroll
        for (int nt = 0; nt < 8; nt++)
#pragma unroll
            for (int r = 0; r < 4; r++) c[mt][nt][r] = 0.f;

    const int nIter = K >> 5;   // K/32

    // tile copy lambdas
    auto issueA = [&](int stage, int k0) {
#pragma unroll
        for (int i = 0; i < 4; i++) {
            int idx = tid + i * 256;        // 0..1023
            int row = idx >> 3;             // 0..127
            int c4  = idx & 7;              // 0..7
            cp16(&As[stage][row * GA_STRIDE + c4 * 4],
                 A + (long)(bm + row) * K + k0 + c4 * 4);
        }
    };
    auto issueB = [&](int stage, int k0) {
#pragma unroll
        for (int i = 0; i < 8; i++) {
            int idx  = tid + i * 256;       // 0..2047
            int krow = idx >> 6;            // 0..31
            int c4   = idx & 63;            // 0..63
            cp16(&Bs[stage][krow * GB_STRIDE + c4 * 4],
                 B + (long)(k0 + krow) * N + bn + c4 * 4);
        }
    };

    issueA(0, 0);
    issueB(0, 0);
    asm volatile("cp.async.commit_group;");

    for (int it = 0; it < nIter; it++) {
        if (it + 1 < nIter) {
            int nb = (it + 1) & 1;
            issueA(nb, (it + 1) << 5);
            issueB(nb, (it + 1) << 5);
            asm volatile("cp.async.commit_group;");
            asm volatile("cp.async.wait_group 1;");
        } else {
            asm volatile("cp.async.wait_group 0;");
        }
        __syncthreads();

        const int st = it & 1;
        const float* Ab = As[st];
        const float* Bb = Bs[st];
#pragma unroll
        for (int ks = 0; ks < 4; ks++) {
            uint32_t a[4][4];
#pragma unroll
            for (int mt = 0; mt < 4; mt++) {
                const float* ap = Ab + (wm + mt * 16 + g) * GA_STRIDE + ks * 8;
                a[mt][0] = __float_as_uint(ap[tig]);
                a[mt][1] = __float_as_uint(ap[8 * GA_STRIDE + tig]);
                a[mt][2] = __float_as_uint(ap[tig + 4]);
                a[mt][3] = __float_as_uint(ap[8 * GA_STRIDE + tig + 4]);
            }
            uint32_t b[8][2];
#pragma unroll
            for (int nt = 0; nt < 8; nt++) {
                const float* bp = Bb + (ks * 8 + tig) * GB_STRIDE + wn + nt * 8 + g;
                b[nt][0] = __float_as_uint(bp[0]);
                b[nt][1] = __float_as_uint(bp[4 * GB_STRIDE]);
            }
#pragma unroll
            for (int mt = 0; mt < 4; mt++)
#pragma unroll
                for (int nt = 0; nt < 8; nt++) {
                    asm volatile(
                        "mma.sync.aligned.m16n8k8.row.col.f32.tf32.tf32.f32 "
                        "{%0,%1,%2,%3}, {%4,%5,%6,%7}, {%8,%9}, {%0,%1,%2,%3};"
                        : "+f"(c[mt][nt][0]), "+f"(c[mt][nt][1]),
                          "+f"(c[mt][nt][2]), "+f"(c[mt][nt][3])
                        : "r"(a[mt][0]), "r"(a[mt][1]), "r"(a[mt][2]), "r"(a[mt][3]),
                          "r"(b[nt][0]), "r"(b[nt][1]));
                }
        }
        __syncthreads();
    }

    // epilogue
#pragma unroll
    for (int mt = 0; mt < 4; mt++) {
        int r0 = bm + wm + mt * 16 + g;
#pragma unroll
        for (int nt = 0; nt < 8; nt++) {
            int col = bn + wn + nt * 8 + tig * 2;
            float x0 = c[mt][nt][0], x1 = c[mt][nt][1];
            float x2 = c[mt][nt][2], x3 = c[mt][nt][3];
            if (SILU) {
                x0 = x0 / (1.f + __expf(-x0));
                x1 = x1 / (1.f + __expf(-x1));
                x2 = x2 / (1.f + __expf(-x2));
                x3 = x3 / (1.f + __expf(-x3));
            }
            *(float2*)(C + (long)r0 * N + col)       = make_float2(x0, x1);
            *(float2*)(C + (long)(r0 + 8) * N + col) = make_float2(x2, x3);
        }
    }
}

// ---------------- low-rank stage 1: R[M,16] = A[M,K] @ W[K,16] ----------------
// 512 blocks x 8 warps, one row per warp.
__global__ __launch_bounds__(256) void lowrank1_kernel(
    const float* __restrict__ A, const float* __restrict__ W,
    float* __restrict__ Rt, int K)
{
    const int warp = threadIdx.x >> 5;
    const int lane = threadIdx.x & 31;
    const int m = blockIdx.x * 8 + warp;
    const float* ap = A + (long)m * K;

    float acc[16];
#pragma unroll
    for (int n = 0; n < 16; n++) acc[n] = 0.f;

    for (int k = lane; k < K; k += 32) {
        float a = ap[k];
        const float4* wr = (const float4*)(W + (long)k * 16);
        float4 w0 = wr[0], w1 = wr[1], w2 = wr[2], w3 = wr[3];
        acc[0]  += a * w0.x; acc[1]  += a * w0.y; acc[2]  += a * w0.z; acc[3]  += a * w0.w;
        acc[4]  += a * w1.x; acc[5]  += a * w1.y; acc[6]  += a * w1.z; acc[7]  += a * w1.w;
        acc[8]  += a * w2.x; acc[9]  += a * w2.y; acc[10] += a * w2.z; acc[11] += a * w2.w;
        acc[12] += a * w3.x; acc[13] += a * w3.y; acc[14] += a * w3.z; acc[15] += a * w3.w;
    }
#pragma unroll
    for (int n = 0; n < 16; n++) {
        float v = acc[n];
        v += __shfl_xor_sync(0xffffffffu, v, 16);
        v += __shfl_xor_sync(0xffffffffu, v, 8);
        v += __shfl_xor_sync(0xffffffffu, v, 4);
        v += __shfl_xor_sync(0xffffffffu, v, 2);
        v += __shfl_xor_sync(0xffffffffu, v, 1);
        if (lane == 0) Rt[(long)m * 16 + n] = v;
    }
}

// ---------------- low-rank stage 2: Out = act(R[M,16] @ W2[16,N] + b) ----------------
__global__ __launch_bounds__(256) void lowrank2_kernel(
    const float* __restrict__ Rt, const float* __restrict__ W2,
    const float* __restrict__ bias, float* __restrict__ Out,
    int NOUT, int mode)
{
    int idx = blockIdx.x * 256 + threadIdx.x;
    int m = idx / NOUT;
    int n = idx - m * NOUT;
    const float* r = Rt + (long)m * 16;
    float acc = bias[n];
#pragma unroll
    for (int j = 0; j < 16; j++) acc += r[j] * W2[(long)j * NOUT + n];
    if (mode) {
        float x = acc;
        float ls = (x >= 0.f) ? -log1pf(__expf(-x)) : (x - log1pf(__expf(x)));
        acc = ls * GLN_INV;
    }
    Out[idx] = acc;
}

// ---------------- GLA chunked recurrence (unchanged from R1) ----------------
#define OFF_Q  0
#define OFF_K  4160
#define OFF_A  8320
#define OFF_V  12480
#define OFF_S  14592
#define OFF_GL 16704
#define SM_FLOATS 16768
#define SM_BYTES  (SM_FLOATS * 4)

__global__ __launch_bounds__(256) void gla_kernel(
    const float* __restrict__ Q, const float* __restrict__ Kx,
    const float* __restrict__ V, const float* __restrict__ GK,
    float* __restrict__ O)
{
    extern __shared__ float sm[];
    float* sq  = sm + OFF_Q;
    float* sk  = sm + OFF_K;
    float* sA  = sm + OFF_A;
    float* sv  = sm + OFF_V;
    float* sS  = sm + OFF_S;
    float* sGl = sm + OFF_GL;

    const int tid = threadIdx.x;
    const int s  = blockIdx.x & 3;
    const int bh = blockIdx.x >> 2;
    const int h  = bh & 15;
    const int b  = bh >> 4;
    const int e0 = s * 32;

    const int cb = tid & 63;
    const int eg = tid >> 6;

    for (int i = tid; i < 64 * 33; i += 256) sS[i] = 0.f;

    for (int ch = 0; ch < NCC; ch++) {
        __syncthreads();
        const long base = ((long)(b * TT + ch * 64) * HH + h);
        const float* qp  = Q  + base * DKq;
        const float* kp  = Kx + base * DKq;
        const float* gp  = GK + base * DKq;
        const float* vp  = V  + base * DVv + e0;

#pragma unroll
        for (int w = 0; w < 4; w++) {
            int f = w * 256 + tid;
            int c = f >> 4;
            int dq = (f & 15) << 2;
            float4 a4 = *(const float4*)(qp + (long)c * 1024 + dq);
            sq[c*65+dq]=a4.x; sq[c*65+dq+1]=a4.y; sq[c*65+dq+2]=a4.z; sq[c*65+dq+3]=a4.w;
            float4 b4 = *(const float4*)(kp + (long)c * 1024 + dq);
            sk[c*65+dq]=b4.x; sk[c*65+dq+1]=b4.y; sk[c*65+dq+2]=b4.z; sk[c*65+dq+3]=b4.w;
            float4 g4 = *(const float4*)(gp + (long)c * 1024 + dq);
            sA[c*65+dq]=g4.x; sA[c*65+dq+1]=g4.y; sA[c*65+dq+2]=g4.z; sA[c*65+dq+3]=g4.w;
        }
#pragma unroll
        for (int w = 0; w < 2; w++) {
            int f = w * 256 + tid;
            int c = f >> 3;
            int eq = (f & 7) << 2;
            float4 v4 = *(const float4*)(vp + (long)c * 2048 + eq);
            sv[c*33+eq]=v4.x; sv[c*33+eq+1]=v4.y; sv[c*33+eq+2]=v4.z; sv[c*33+eq+3]=v4.w;
        }
        __syncthreads();

        if (tid < 64) {
            int d = tid;
            float acc = 0.f;
            for (int c = 0; c < 64; c++) {
                acc += sA[c*65 + d];
                sA[c*65 + d] = acc;
            }
            sGl[d] = acc;
        }
        __syncthreads();

#pragma unroll
        for (int w = 0; w < 16; w++) {
            int f = w * 256 + tid;
            int c = f >> 6;
            int d = f & 63;
            float G = sA[c*65 + d];
            sq[c*65 + d] *= __expf(G) * 0.125f;
            sk[c*65 + d] *= __expf(-G);
        }
        if (tid < 64) sGl[tid] = __expf(sGl[tid]);
        __syncthreads();

        float o_r[8];
#pragma unroll
        for (int j = 0; j < 8; j++) o_r[j] = 0.f;
        {
            const int c = cb;
#pragma unroll 4
            for (int d = 0; d < 64; d++) {
                float qv = sq[c*65 + d];
                const float* Srow = &sS[d*33 + eg*8];
#pragma unroll
                for (int j = 0; j < 8; j++) o_r[j] += qv * Srow[j];
            }
        }
        {
            const int c = cb;
            const int jbase = eg * 16;
            float a[16];
#pragma unroll
            for (int jj = 0; jj < 16; jj++) a[jj] = 0.f;
#pragma unroll 2
            for (int d = 0; d < 64; d++) {
                float qv = sq[c*65 + d];
#pragma unroll
                for (int jj = 0; jj < 16; jj++)
                    a[jj] += qv * sk[(jbase + jj)*65 + d];
            }
#pragma unroll
            for (int jj = 0; jj < 16; jj++)
                sA[c*65 + jbase + jj] = (jbase + jj <= c) ? a[jj] : 0.f;
        }
        __syncthreads();

        {
            const int c = cb;
            for (int j64 = 0; j64 <= c; j64++) {
                float a = sA[c*65 + j64];
                const float* vr = &sv[j64*33 + eg*8];
#pragma unroll
                for (int j = 0; j < 8; j++) o_r[j] += a * vr[j];
            }
            float* op = O + (base + (long)c * HH) * DVv + e0 + eg * 8;
            float4 w0 = make_float4(o_r[0], o_r[1], o_r[2], o_r[3]);
            float4 w1 = make_float4(o_r[4], o_r[5], o_r[6], o_r[7]);
            *(float4*)(op)     = w0;
            *(float4*)(op + 4) = w1;
        }
        {
            const int d = cb;
            float* Srow = &sS[d*33 + eg*8];
            float acc[8];
#pragma unroll
            for (int j = 0; j < 8; j++) acc[j] = Srow[j];
#pragma unroll 4
            for (int c64 = 0; c64 < 64; c64++) {
                float kv = sk[c64*65 + d];
                const float* vr = &sv[c64*33 + eg*8];
#pragma unroll
                for (int j = 0; j < 8; j++) acc[j] += kv * vr[j];
            }
            float eGl = sGl[d];
#pragma unroll
            for (int j = 0; j < 8; j++) Srow[j] = acc[j] * eGl;
        }
    }
}

// ---------------- RMS norm + sigmoid gate (in place, outputs tf32-rounded) ---
__global__ __launch_bounds__(256) void rmsgate_kernel(
    float* __restrict__ O, const float* __restrict__ G,
    const float* __restrict__ gw)
{
    int row = blockIdx.x * 8 + (threadIdx.x >> 5);
    int lane = threadIdx.x & 31;
    long basei = (long)row * 128 + lane * 4;
    float4 o4 = *(float4*)&O[basei];
    float ss = o4.x*o4.x + o4.y*o4.y + o4.z*o4.z + o4.w*o4.w;
    ss += __shfl_xor_sync(0xffffffffu, ss, 16);
    ss += __shfl_xor_sync(0xffffffffu, ss, 8);
    ss += __shfl_xor_sync(0xffffffffu, ss, 4);
    ss += __shfl_xor_sync(0xffffffffu, ss, 2);
    ss += __shfl_xor_sync(0xffffffffu, ss, 1);
    float rr = rsqrtf(ss * (1.f / 128.f) + EPSL);
    float4 g4 = *(const float4*)&G[basei];
    float4 w4 = *(const float4*)&gw[lane * 4];
    o4.x = f2tf32(o4.x * rr * w4.x / (1.f + __expf(-g4.x)));
    o4.y = f2tf32(o4.y * rr * w4.y / (1.f + __expf(-g4.y)));
    o4.z = f2tf32(o4.z * rr * w4.z / (1.f + __expf(-g4.z)));
    o4.w = f2tf32(o4.w * rr * w4.w / (1.f + __expf(-g4.w)));
    *(float4*)&O[basei] = o4;
}

// ---------------- launch ----------------
extern "C" void kernel_launch(void* const* d_in, const int* in_sizes, int n_in,
                              void* d_out, int out_size)
{
    const float* hs    = (const float*)d_in[0];
    const float* Wq    = (const float*)d_in[1];
    const float* Wk    = (const float*)d_in[2];
    const float* Wv    = (const float*)d_in[3];
    const float* Wgk1  = (const float*)d_in[4];
    const float* Wgk2  = (const float*)d_in[5];
    const float* bgk2  = (const float*)d_in[6];
    const float* Wg1   = (const float*)d_in[7];
    const float* Wg2   = (const float*)d_in[8];
    const float* bg2   = (const float*)d_in[9];
    const float* Wo    = (const float*)d_in[10];
    const float* gnw   = (const float*)d_in[11];
    float* out = (float*)d_out;

    float *pq, *pk, *pv, *pgk, *pr1, *pr2, *pg, *po;
    float *phsr, *pwqr, *pwkr, *pwvr, *pwor;
    cudaGetSymbolAddress((void**)&pq,  g_q);
    cudaGetSymbolAddress((void**)&pk,  g_k);
    cudaGetSymbolAddress((void**)&pv,  g_v);
    cudaGetSymbolAddress((void**)&pgk, g_gk);
    cudaGetSymbolAddress((void**)&pr1, g_r1);
    cudaGetSymbolAddress((void**)&pr2, g_r2);
    cudaGetSymbolAddress((void**)&pg,  g_g);
    cudaGetSymbolAddress((void**)&po,  g_o);
    cudaGetSymbolAddress((void**)&phsr, g_hsr);
    cudaGetSymbolAddress((void**)&pwqr, g_wqr);
    cudaGetSymbolAddress((void**)&pwkr, g_wkr);
    cudaGetSymbolAddress((void**)&pwvr, g_wvr);
    cudaGetSymbolAddress((void**)&pwor, g_wor);

    cudaFuncSetAttribute(tf32gemm_kernel<true>,  cudaFuncAttributeMaxDynamicSharedMemorySize, GSM_BYTES);
    cudaFuncSetAttribute(tf32gemm_kernel<false>, cudaFuncAttributeMaxDynamicSharedMemorySize, GSM_BYTES);
    cudaFuncSetAttribute(gla_kernel, cudaFuncAttributeMaxDynamicSharedMemorySize, SM_BYTES);

    // tf32 pre-rounding of GEMM operands
    round_tf32_kernel<<<(MM*DD/4 + 255)/256, 256>>>(hs, phsr, MM*DD/4);
    round_tf32_kernel<<<(DD*NQK/4 + 255)/256, 256>>>(Wq, pwqr, DD*NQK/4);
    round_tf32_kernel<<<(DD*NQK/4 + 255)/256, 256>>>(Wk, pwkr, DD*NQK/4);
    round_tf32_kernel<<<(DD*NV/4 + 255)/256, 256>>>(Wv, pwvr, DD*NV/4);
    round_tf32_kernel<<<(NV*DD/4 + 255)/256, 256>>>(Wo, pwor, NV*DD/4);

    // projections with silu (tensor core tf32)
    {
        dim3 grid(NQK / 256, MM / 128);
        tf32gemm_kernel<true><<<grid, 256, GSM_BYTES>>>(phsr, pwqr, pq, MM, NQK, DD);
        tf32gemm_kernel<true><<<grid, 256, GSM_BYTES>>>(phsr, pwkr, pk, MM, NQK, DD);
    }
    {
        dim3 grid(NV / 256, MM / 128);
        tf32gemm_kernel<true><<<grid, 256, GSM_BYTES>>>(phsr, pwvr, pv, MM, NV, DD);
    }
    // low-rank gk gate (full fp32 path, original hs)
    lowrank1_kernel<<<MM / 8, 256>>>(hs, Wgk1, pr1, DD);
    lowrank2_kernel<<<(MM * NQK) / 256, 256>>>(pr1, Wgk2, bgk2, pgk, NQK, 1);
    // low-rank output gate
    lowrank1_kernel<<<MM / 8, 256>>>(hs, Wg1, pr2, DD);
    lowrank2_kernel<<<(MM * NV) / 256, 256>>>(pr2, Wg2, bg2, pg, NV, 0);

    // chunked GLA
    gla_kernel<<<BB * HH * 4, 256, SM_BYTES>>>(pq, pk, pv, pgk, po);

    // rms norm + gate (rounds output to tf32 for the Wo GEMM)
    rmsgate_kernel<<<(MM * HH) / 8, 256>>>(po, pg, gnw);

    // output projection
    {
        dim3 grid(DD / 256, MM / 128);
        tf32gemm_kernel<false><<<grid, 256, GSM_BYTES>>>(po, pwor, out, MM, DD, NV);
    }
    (void)in_sizes; (void)n_in; (void)out_size;
}